// round 2
// baseline (speedup 1.0000x reference)
#include <cuda_runtime.h>

typedef unsigned long long u64;

#define U_  128
#define D_  64
#define T_  128
#define B_  2048
#define BM  32
#define NTH 256

// ---- fast activations (abs err ~3e-7, overflow-safe at both ends) ----
__device__ __forceinline__ float fsig(float x) {
    return __fdividef(1.f, 1.f + __expf(-x));
}
__device__ __forceinline__ float ftanh_(float x) {
    // tanh(x) = 2*sigmoid(2x) - 1 ; saturates cleanly for |x| large (exp -> 0 or inf)
    return __fdividef(2.f, 1.f + __expf(-2.f * x)) - 1.f;
}

// ---- packed f32x2 helpers (sm_103a) ----
__device__ __forceinline__ void ffma2(u64 &d, u64 a, u64 b) {
    asm("fma.rn.f32x2 %0, %1, %2, %0;" : "+l"(d) : "l"(a), "l"(b));
}
__device__ __forceinline__ u64 splat2(float w) {
    unsigned wu = __float_as_uint(w);
    u64 r;
    asm("mov.b64 %0, {%1, %1};" : "=l"(r) : "r"(wu));
    return r;
}
__device__ __forceinline__ void unpack2(u64 v, float &lo, float &hi) {
    unsigned a, b;
    asm("mov.b64 {%0, %1}, %2;" : "=r"(a), "=r"(b) : "l"(v));
    lo = __uint_as_float(a);
    hi = __uint_as_float(b);
}

// Grid: (B/BM, 2). blockIdx.y: 0 = SNN path (input_feature_st), 1 = ANN path (input_features_sc).
// Thread tile: 4 batch-pairs (8 batch rows) x 2 units x 4 gates = 32 f32x2 accumulators.
// tid -> pgq = tid>>6 (batch-pair group, cols cb=8*pgq), ug = tid&63 (units u0=2*ug .. +1).
__global__ void __launch_bounds__(NTH, 1)
lstm_dual_kernel(const float* __restrict__ x_st,
                 const float* __restrict__ x_sc,
                 const float* __restrict__ Wih,
                 const float* __restrict__ Whh,
                 const float* __restrict__ bih,
                 const float* __restrict__ bhh,
                 const float* __restrict__ gamma_,
                 const float* __restrict__ beta_,
                 const float* __restrict__ mean_,
                 const float* __restrict__ var_,
                 float* __restrict__ out)
{
    // [k][batch] layout so a batch-pair is one 8B broadcast LDS
    __shared__ float hs[2][U_][BM];   // double-buffered hidden state
    __shared__ float xs[2][D_][BM];   // double-buffered input tile

    const int tid = threadIdx.x;
    const int pgq = tid >> 6;          // 0..3
    const int ug  = tid & 63;          // 0..63
    const int u0  = ug * 2;
    const int cb  = pgq * 8;

    const int path  = blockIdx.y;      // 0 = SNN(st), 1 = ANN(sc)
    const int bbase = blockIdx.x * BM;
    const float* __restrict__ xin = (path == 0) ? x_st : x_sc;

    // combined bias for this thread's 8 gate rows
    float bias[4][2];
    #pragma unroll
    for (int g = 0; g < 4; g++)
        #pragma unroll
        for (int uu = 0; uu < 2; uu++) {
            const int row = g * U_ + u0 + uu;
            bias[g][uu] = bih[row] + bhh[row];
        }

    // zero both h buffers (h0 = 0; SNN first-step "spk" input is 0 too)
    for (int i = tid; i < 2 * U_ * BM; i += NTH) ((float*)hs)[i] = 0.f;

    // x staging map: each thread stages 8 consecutive k's of one batch row
    const int xb = tid >> 3;
    const int xk = (tid & 7) * 8;
    const float* __restrict__ xsrc = xin + ((size_t)(bbase + xb) * T_) * D_ + xk;

    // preload x for t = 0
    {
        float4 v0 = *(const float4*)(xsrc);
        float4 v1 = *(const float4*)(xsrc + 4);
        xs[0][xk + 0][xb] = v0.x; xs[0][xk + 1][xb] = v0.y;
        xs[0][xk + 2][xb] = v0.z; xs[0][xk + 3][xb] = v0.w;
        xs[0][xk + 4][xb] = v1.x; xs[0][xk + 5][xb] = v1.y;
        xs[0][xk + 6][xb] = v1.z; xs[0][xk + 7][xb] = v1.w;
    }

    // register-resident per-element state: [pair][lane][unit]
    float cst[4][2][2];   // LSTM cell c
    float aux[4][2][2];   // SNN membrane potential
    float acm[4][2][2];   // running sum (h for ANN, spikes for SNN)
    #pragma unroll
    for (int p = 0; p < 4; p++)
        #pragma unroll
        for (int l = 0; l < 2; l++)
            #pragma unroll
            for (int uu = 0; uu < 2; uu++) {
                cst[p][l][uu] = 0.f; aux[p][l][uu] = 0.f; acm[p][l][uu] = 0.f;
            }

    for (int t = 0; t < T_; t++) {
        const int cur = t & 1, nxt = cur ^ 1;
        __syncthreads();   // h[cur] and xs[cur] written last iter are now visible

        // prefetch next timestep's x into registers (stored to smem post-compute)
        float4 xv0, xv1;
        const bool pf = (t + 1 < T_);
        if (pf) {
            const float* s = xsrc + (size_t)(t + 1) * D_;
            xv0 = *(const float4*)(s);
            xv1 = *(const float4*)(s + 4);
        }

        // gate accumulators, init = bias (both packed lanes)
        u64 acc[4][4][2];  // [pair][gate][unit]
        #pragma unroll
        for (int p = 0; p < 4; p++)
            #pragma unroll
            for (int g = 0; g < 4; g++)
                #pragma unroll
                for (int uu = 0; uu < 2; uu++)
                    acc[p][g][uu] = splat2(bias[g][uu]);

        // ---- x @ Wih^T ----
        #pragma unroll 2
        for (int k4 = 0; k4 < D_; k4 += 4) {
            u64 a[4][4];
            #pragma unroll
            for (int p = 0; p < 4; p++)
                #pragma unroll
                for (int kk = 0; kk < 4; kk++)
                    a[p][kk] = *(const u64*)&xs[cur][k4 + kk][cb + 2 * p];
            #pragma unroll
            for (int g = 0; g < 4; g++) {
                #pragma unroll
                for (int uu = 0; uu < 2; uu++) {
                    const float4 w = *(const float4*)(Wih + ((size_t)(g * U_ + u0 + uu) * D_ + k4));
                    const float wf[4] = {w.x, w.y, w.z, w.w};
                    #pragma unroll
                    for (int kk = 0; kk < 4; kk++) {
                        const u64 w2 = splat2(wf[kk]);
                        #pragma unroll
                        for (int p = 0; p < 4; p++)
                            ffma2(acc[p][g][uu], w2, a[p][kk]);
                    }
                }
            }
        }

        // ---- h @ Whh^T ----
        #pragma unroll 2
        for (int k4 = 0; k4 < U_; k4 += 4) {
            u64 a[4][4];
            #pragma unroll
            for (int p = 0; p < 4; p++)
                #pragma unroll
                for (int kk = 0; kk < 4; kk++)
                    a[p][kk] = *(const u64*)&hs[cur][k4 + kk][cb + 2 * p];
            #pragma unroll
            for (int g = 0; g < 4; g++) {
                #pragma unroll
                for (int uu = 0; uu < 2; uu++) {
                    const float4 w = *(const float4*)(Whh + ((size_t)(g * U_ + u0 + uu) * U_ + k4));
                    const float wf[4] = {w.x, w.y, w.z, w.w};
                    #pragma unroll
                    for (int kk = 0; kk < 4; kk++) {
                        const u64 w2 = splat2(wf[kk]);
                        #pragma unroll
                        for (int p = 0; p < 4; p++)
                            ffma2(acc[p][g][uu], w2, a[p][kk]);
                    }
                }
            }
        }

        // ---- activations, state update, h write ----
        #pragma unroll
        for (int uu = 0; uu < 2; uu++) {
            float hv[4][2];
            #pragma unroll
            for (int p = 0; p < 4; p++) {
                float glo[4], ghi[4];
                #pragma unroll
                for (int g = 0; g < 4; g++) unpack2(acc[p][g][uu], glo[g], ghi[g]);
                #pragma unroll
                for (int l = 0; l < 2; l++) {
                    const float* gg = l ? ghi : glo;
                    const float iv = fsig(gg[0]);
                    const float fv = fsig(gg[1]);
                    const float gv = ftanh_(gg[2]);
                    const float ov = fsig(gg[3]);
                    const float c  = fv * cst[p][l][uu] + iv * gv;
                    cst[p][l][uu] = c;
                    const float hval = ov * ftanh_(c);
                    if (path == 0) {               // SNN: integrate-and-fire
                        const float m  = aux[p][l][uu] + hval;
                        const float sp = (m >= 1.f) ? 1.f : 0.f;
                        aux[p][l][uu] = m - sp;    // soft reset (VTH = 1)
                        acm[p][l][uu] += sp;
                        hv[p][l] = sp;             // spike feeds next step's gates
                    } else {                       // ANN: standard LSTM
                        acm[p][l][uu] += hval;
                        hv[p][l] = hval;
                    }
                }
            }
            const float4 s0 = make_float4(hv[0][0], hv[0][1], hv[1][0], hv[1][1]);
            const float4 s1 = make_float4(hv[2][0], hv[2][1], hv[3][0], hv[3][1]);
            *(float4*)&hs[nxt][u0 + uu][cb]     = s0;
            *(float4*)&hs[nxt][u0 + uu][cb + 4] = s1;
        }

        // commit prefetched x for t+1
        if (pf) {
            xs[nxt][xk + 0][xb] = xv0.x; xs[nxt][xk + 1][xb] = xv0.y;
            xs[nxt][xk + 2][xb] = xv0.z; xs[nxt][xk + 3][xb] = xv0.w;
            xs[nxt][xk + 4][xb] = xv1.x; xs[nxt][xk + 5][xb] = xv1.y;
            xs[nxt][xk + 6][xb] = xv1.z; xs[nxt][xk + 7][xb] = xv1.w;
        }
    }

    // ---- epilogue: temporal mean + BatchNorm (eval), write [2, B, U] ----
    const float invT = 1.f / (float)T_;
    #pragma unroll
    for (int uu = 0; uu < 2; uu++) {
        const int u = u0 + uu;
        const float sc = rsqrtf(var_[u] + 1e-5f) * gamma_[u];
        const float mb = mean_[u];
        const float bt = beta_[u];
        #pragma unroll
        for (int p = 0; p < 4; p++)
            #pragma unroll
            for (int l = 0; l < 2; l++) {
                const int b = bbase + cb + 2 * p + l;
                const float pooled = acm[p][l][uu] * invT;
                out[((size_t)path * B_ + b) * U_ + u] = (pooled - mb) * sc + bt;
            }
    }
}

extern "C" void kernel_launch(void* const* d_in, const int* in_sizes, int n_in,
                              void* d_out, int out_size) {
    (void)in_sizes; (void)n_in; (void)out_size;
    dim3 grid(B_ / BM, 2);
    lstm_dual_kernel<<<grid, NTH>>>(
        (const float*)d_in[0],  // input_feature_st  (SNN)
        (const float*)d_in[1],  // input_features_sc (ANN)
        (const float*)d_in[2],  // W_ih [512,64]
        (const float*)d_in[3],  // W_hh [512,128]
        (const float*)d_in[4],  // b_ih
        (const float*)d_in[5],  // b_hh
        (const float*)d_in[6],  // bn_gamma
        (const float*)d_in[7],  // bn_beta
        (const float*)d_in[8],  // bn_mean
        (const float*)d_in[9],  // bn_var
        (float*)d_out);
}

// round 3
// speedup vs baseline: 3.2846x; 3.2846x over previous
#include <cuda_runtime.h>

typedef unsigned long long u64;

#define U_    128
#define D_    64
#define T_    128
#define B_    2048
#define BM    32
#define NTH   256
#define KTOT  192
#define SLABK 24
#define NSLAB 8
#define ROWS  512

// smem: A[2][KTOT][BM] + W[2][SLABK][ROWS]
#define A_FLOATS (2 * KTOT * BM)
#define W_FLOATS (2 * SLABK * ROWS)
#define SMEM_BYTES ((A_FLOATS + W_FLOATS) * 4)

// k-major weights (WT[k][row], rows = gate*128 + unit) + fused bias
__device__ float g_WT[KTOT * ROWS];
__device__ float g_bias[ROWS];

// ---- fast activations ----
__device__ __forceinline__ float fsig(float x) {
    return __fdividef(1.f, 1.f + __expf(-x));
}
__device__ __forceinline__ float ftanh_(float x) {
    return __fdividef(2.f, 1.f + __expf(-2.f * x)) - 1.f;
}

// ---- packed f32x2 (sm_103a) ----
__device__ __forceinline__ void ffma2(u64 &d, u64 a, u64 b) {
    asm("fma.rn.f32x2 %0, %1, %2, %0;" : "+l"(d) : "l"(a), "l"(b));
}
__device__ __forceinline__ u64 splat2f(float x) {
    u64 r;
    asm("mov.b64 %0, {%1, %1};" : "=l"(r) : "f"(x));
    return r;
}
__device__ __forceinline__ void unpack2(u64 v, float &lo, float &hi) {
    asm("mov.b64 {%0, %1}, %2;" : "=f"(lo), "=f"(hi) : "l"(v));
}

// ---- cp.async ----
__device__ __forceinline__ unsigned smem_u32(const void* p) {
    return (unsigned)__cvta_generic_to_shared(p);
}
__device__ __forceinline__ void cp16(unsigned d, const void* s) {
    asm volatile("cp.async.cg.shared.global [%0], [%1], 16;" :: "r"(d), "l"(s));
}
#define CP_COMMIT() asm volatile("cp.async.commit_group;")
#define CP_WAIT1()  asm volatile("cp.async.wait_group 1;")

// prep: WT[k][r] = (k<64 ? Wih[r][k] : Whh[r][k-64]); bias[r] = bih[r]+bhh[r]
__global__ void prep_kernel(const float* __restrict__ Wih, const float* __restrict__ Whh,
                            const float* __restrict__ bih, const float* __restrict__ bhh) {
    const int r = blockIdx.x;
    const int k = threadIdx.x;
    float v = (k < D_) ? Wih[r * D_ + k] : Whh[r * U_ + (k - D_)];
    g_WT[k * ROWS + r] = v;
    if (k == 0) g_bias[r] = bih[r] + bhh[r];
}

// Main kernel. Grid (B/BM, 2); path 0 = SNN (x_st), 1 = ANN (x_sc).
// Warp w owns units [16w, 16w+16). Lane = bg(0..3)*8 + rg(0..7):
//   rg -> unit pair u0 = 16w + 2rg (packed in f32x2 lanes)
//   bg -> 8 batch columns cb = 8*bg
// acc[b][g] : 8 batch x 4 gates, each u64 = gates for (u0, u0+1).
__global__ void __launch_bounds__(NTH, 1)
lstm_main(const float* __restrict__ x_st, const float* __restrict__ x_sc,
          const float* __restrict__ gamma_, const float* __restrict__ beta_,
          const float* __restrict__ mean_, const float* __restrict__ var_,
          float* __restrict__ out)
{
    extern __shared__ float smf[];
    float* Abuf = smf;                  // [2][KTOT][BM]
    float* Wbuf = smf + A_FLOATS;       // [2][SLABK][ROWS]

    const int tid  = threadIdx.x;
    const int warp = tid >> 5;
    const int lane = tid & 31;
    const int bg   = lane >> 3;
    const int rg   = lane & 7;
    const int u0   = warp * 16 + rg * 2;
    const int cb   = bg * 8;

    const int path  = blockIdx.y;
    const int bbase = blockIdx.x * BM;
    const float* __restrict__ xin = (path == 0) ? x_st : x_sc;

    // fused bias pairs (u0, u0+1) per gate
    u64 bias2[4];
    #pragma unroll
    for (int g = 0; g < 4; g++)
        bias2[g] = *(const u64*)&g_bias[g * U_ + u0];

    // zero h region (k in [64,192)) of both A buffers
    for (int i = tid; i < 2 * U_ * BM; i += NTH) {
        const int buf = i / (U_ * BM);
        const int j   = i % (U_ * BM);
        Abuf[buf * KTOT * BM + (D_ + j / BM) * BM + (j % BM)] = 0.f;
    }

    // x staging: thread stages 8 consecutive k's of one batch row
    const int xb = tid >> 3;
    const int xk = (tid & 7) * 8;
    const float* __restrict__ xsrc = xin + ((size_t)(bbase + xb) * T_) * D_ + xk;

    {   // preload t=0 x into A[0]
        float4 v0 = *(const float4*)(xsrc);
        float4 v1 = *(const float4*)(xsrc + 4);
        float* a0 = Abuf + xk * BM + xb;
        a0[0 * BM] = v0.x; a0[1 * BM] = v0.y; a0[2 * BM] = v0.z; a0[3 * BM] = v0.w;
        a0[4 * BM] = v1.x; a0[5 * BM] = v1.y; a0[6 * BM] = v1.z; a0[7 * BM] = v1.w;
    }

    // prologue: stage slabs 0,1 (48KB each, fully coalesced)
    const unsigned wsm0 = smem_u32(Wbuf);
    #pragma unroll
    for (int s = 0; s < 2; s++) {
        unsigned    dst = wsm0 + (unsigned)(s * SLABK * ROWS * 4) + tid * 16;
        const char* src = (const char*)g_WT + (size_t)s * SLABK * ROWS * 4 + tid * 16;
        #pragma unroll
        for (int i = 0; i < 12; i++) cp16(dst + i * 4096, src + i * 4096);
        CP_COMMIT();
    }

    // per-element state: [batch 8][unit lane 2]
    float cst[8][2], mem_[8][2], acm[8][2];
    #pragma unroll
    for (int b = 0; b < 8; b++)
        #pragma unroll
        for (int uu = 0; uu < 2; uu++) {
            cst[b][uu] = 0.f; mem_[b][uu] = 0.f; acm[b][uu] = 0.f;
        }

    u64 acc[8][4];

    for (int t = 0; t < T_; t++) {
        const int cur = t & 1, nxt = cur ^ 1;
        const float* A_cur = Abuf + cur * KTOT * BM;

        #pragma unroll
        for (int b = 0; b < 8; b++)
            #pragma unroll
            for (int g = 0; g < 4; g++)
                acc[b][g] = bias2[g];

        // prefetch next timestep's x
        float4 xv0, xv1;
        const bool pf = (t + 1 < T_);
        if (pf) {
            const float* s = xsrc + (size_t)(t + 1) * D_;
            xv0 = *(const float4*)(s);
            xv1 = *(const float4*)(s + 4);
        }

        for (int s = 0; s < NSLAB; s++) {
            const int step = t * NSLAB + s;
            CP_WAIT1();
            __syncthreads();   // slab 'step' visible to all; A_cur writes visible

            const float* Wb = Wbuf + (step & 1) * SLABK * ROWS;
            const float* Ak = A_cur + (s * SLABK) * BM;

            #pragma unroll 4
            for (int kk = 0; kk < SLABK; kk++) {
                const float4 a0 = *(const float4*)(Ak + kk * BM + cb);
                const float4 a1 = *(const float4*)(Ak + kk * BM + cb + 4);
                u64 av[8];
                av[0] = splat2f(a0.x); av[1] = splat2f(a0.y);
                av[2] = splat2f(a0.z); av[3] = splat2f(a0.w);
                av[4] = splat2f(a1.x); av[5] = splat2f(a1.y);
                av[6] = splat2f(a1.z); av[7] = splat2f(a1.w);
                #pragma unroll
                for (int g = 0; g < 4; g++) {
                    const u64 w2 = *(const u64*)(Wb + kk * ROWS + g * U_ + u0);
                    #pragma unroll
                    for (int b = 0; b < 8; b++)
                        ffma2(acc[b][g], av[b], w2);
                }
            }
            __syncthreads();   // all done reading Wbuf[step&1] before overwrite

            if (step + 2 < T_ * NSLAB) {
                const int ns = (step + 2) % NSLAB;  // weights repeat every NSLAB
                unsigned    dst = wsm0 + (unsigned)((step & 1) * SLABK * ROWS * 4) + tid * 16;
                const char* src = (const char*)g_WT + (size_t)ns * SLABK * ROWS * 4 + tid * 16;
                #pragma unroll
                for (int i = 0; i < 12; i++) cp16(dst + i * 4096, src + i * 4096);
            }
            CP_COMMIT();
        }

        // ---- activations + state update ----
        float* A_nxt = Abuf + nxt * KTOT * BM;
        float hv[2][8];
        #pragma unroll
        for (int b = 0; b < 8; b++) {
            float gi[2], gf[2], gg[2], go[2];
            unpack2(acc[b][0], gi[0], gi[1]);
            unpack2(acc[b][1], gf[0], gf[1]);
            unpack2(acc[b][2], gg[0], gg[1]);
            unpack2(acc[b][3], go[0], go[1]);
            #pragma unroll
            for (int uu = 0; uu < 2; uu++) {
                const float iv = fsig(gi[uu]);
                const float fv = fsig(gf[uu]);
                const float gv = ftanh_(gg[uu]);
                const float ov = fsig(go[uu]);
                const float c  = fv * cst[b][uu] + iv * gv;
                cst[b][uu] = c;
                const float h = ov * ftanh_(c);
                if (path == 0) {            // SNN integrate-and-fire
                    const float m  = mem_[b][uu] + h;
                    const float sp = (m >= 1.f) ? 1.f : 0.f;
                    mem_[b][uu] = m - sp;   // soft reset, VTH=1
                    acm[b][uu] += sp;
                    hv[uu][b] = sp;
                } else {                    // ANN
                    acm[b][uu] += h;
                    hv[uu][b] = h;
                }
            }
        }
        #pragma unroll
        for (int uu = 0; uu < 2; uu++) {
            float* dst = A_nxt + (D_ + u0 + uu) * BM + cb;
            *(float4*)(dst)     = make_float4(hv[uu][0], hv[uu][1], hv[uu][2], hv[uu][3]);
            *(float4*)(dst + 4) = make_float4(hv[uu][4], hv[uu][5], hv[uu][6], hv[uu][7]);
        }
        if (pf) {
            float* a0 = A_nxt + xk * BM + xb;
            a0[0 * BM] = xv0.x; a0[1 * BM] = xv0.y; a0[2 * BM] = xv0.z; a0[3 * BM] = xv0.w;
            a0[4 * BM] = xv1.x; a0[5 * BM] = xv1.y; a0[6 * BM] = xv1.z; a0[7 * BM] = xv1.w;
        }
    }

    // ---- temporal mean + BatchNorm(eval), out [2, B, U] ----
    const float invT = 1.f / (float)T_;
    #pragma unroll
    for (int uu = 0; uu < 2; uu++) {
        const int u = u0 + uu;
        const float sc = rsqrtf(var_[u] + 1e-5f) * gamma_[u];
        const float mb = mean_[u];
        const float bt = beta_[u];
        #pragma unroll
        for (int b = 0; b < 8; b++) {
            const int bb = bbase + cb + b;
            out[((size_t)path * B_ + bb) * U_ + u] = (acm[b][uu] * invT - mb) * sc + bt;
        }
    }
}

extern "C" void kernel_launch(void* const* d_in, const int* in_sizes, int n_in,
                              void* d_out, int out_size) {
    (void)in_sizes; (void)n_in; (void)out_size;
    cudaFuncSetAttribute(lstm_main, cudaFuncAttributeMaxDynamicSharedMemorySize, SMEM_BYTES);

    prep_kernel<<<ROWS, KTOT>>>(
        (const float*)d_in[2],  // W_ih
        (const float*)d_in[3],  // W_hh
        (const float*)d_in[4],  // b_ih
        (const float*)d_in[5]); // b_hh

    dim3 grid(B_ / BM, 2);
    lstm_main<<<grid, NTH, SMEM_BYTES>>>(
        (const float*)d_in[0],  // input_feature_st  (SNN)
        (const float*)d_in[1],  // input_features_sc (ANN)
        (const float*)d_in[6],  // bn_gamma
        (const float*)d_in[7],  // bn_beta
        (const float*)d_in[8],  // bn_mean
        (const float*)d_in[9],  // bn_var
        (float*)d_out);
}